// round 1
// baseline (speedup 1.0000x reference)
#include <cuda_runtime.h>
#include <cstdint>

#define E_TOT   131072
#define DDIM    128
#define TILE_E  128
#define KC      64
#define NTHREADS 256

// ---- SMEM layout (in floats) ----
#define U_OFF   0        // [128 j][128 e] swizzled, 16384
#define V_OFF   16384    // [128 j][128 e] swizzled, 16384
#define F_OFF   32768    // feat chunk [64 k][128 e],  8192
#define W_OFF   40960    // fc_w chunk [64 k][128 d],  8192
#define S3_OFF  49152    // 128
#define Q3_OFF  49280    // 128
#define CA_OFF  49408    // 16
#define CB_OFF  49424    // 16
#define CD_OFF  49440    // 16
#define ROW_OFF 49456    // 128 ints
#define COL_OFF 49584    // 128 ints
#define TYP_OFF 49712    // 128 ints
#define SMEM_FLOATS 49840
#define SMEM_BYTES  (SMEM_FLOATS * 4)

__device__ __forceinline__ unsigned long long pack_dup(float f) {
    unsigned long long r;
    asm("mov.b64 %0, {%1, %1};" : "=l"(r) : "f"(f));
    return r;
}
__device__ __forceinline__ void fma2(unsigned long long& d,
                                     unsigned long long a,
                                     unsigned long long b) {
    asm("fma.rn.f32x2 %0, %1, %2, %0;" : "+l"(d) : "l"(a), "l"(b));
}
__device__ __forceinline__ float2 unpack2(unsigned long long v) {
    float2 r;
    asm("mov.b64 {%0, %1}, %2;" : "=f"(r.x), "=f"(r.y) : "l"(v));
    return r;
}

extern "C" __global__ void __launch_bounds__(NTHREADS, 1)
conve_kernel(const float* __restrict__ h, const float* __restrict__ g,
             const int* __restrict__ eidx, const int* __restrict__ etype,
             const float* __restrict__ conv_w, const float* __restrict__ conv_b,
             const float* __restrict__ fc_w, const float* __restrict__ fc_b,
             const float* __restrict__ bn1g, const float* __restrict__ bn1b,
             const float* __restrict__ bn1m, const float* __restrict__ bn1v,
             const float* __restrict__ bn3g, const float* __restrict__ bn3b,
             const float* __restrict__ bn3m, const float* __restrict__ bn3v,
             float* __restrict__ out)
{
    extern __shared__ float sm[];
    float* U  = sm + U_OFF;
    float* V  = sm + V_OFF;
    float* F  = sm + F_OFF;
    float* W  = sm + W_OFF;
    float* S3 = sm + S3_OFF;
    float* Q3 = sm + Q3_OFF;
    float* CA = sm + CA_OFF;
    float* CB = sm + CB_OFF;
    float* CD = sm + CD_OFF;
    int* ROW = (int*)(sm + ROW_OFF);
    int* COL = (int*)(sm + COL_OFF);
    int* TYP = (int*)(sm + TYP_OFF);

    const int tid = threadIdx.x;
    const int e0  = blockIdx.x * TILE_E;
    const int tx  = tid & 15;     // dim group 0..15
    const int ty  = tid >> 4;     // edge group 0..15

    // ---- per-CTA parameter prep ----
    if (tid < DDIM) {
        float s = bn3g[tid] * rsqrtf(bn3v[tid] + 1e-5f);
        S3[tid] = s;
        Q3[tid] = fc_b[tid] * s + bn3b[tid] - bn3m[tid] * s;
        ROW[tid] = eidx[e0 + tid];
        COL[tid] = eidx[E_TOT + e0 + tid];
        TYP[tid] = etype[e0 + tid];
    }
    if (tid < 16) {
        float s1 = bn1g[0] * rsqrtf(bn1v[0] + 1e-5f);
        float b1 = bn1b[0] - bn1m[0] * s1;
        float w0 = conv_w[tid * 2], w1 = conv_w[tid * 2 + 1];
        CA[tid] = w0 * s1;
        CB[tid] = w1 * s1;
        CD[tid] = (w0 + w1) * b1 + conv_b[tid];
    }
    __syncthreads();

    // ---- gather subject (h[row]) and relation (g[type]) rows into SMEM,
    //      stored transposed [j][e] with XOR swizzle for conflict-free
    //      fill (j-consecutive STS) AND feat-phase reads (e-consecutive LDS).
#pragma unroll 4
    for (int i = 0; i < 64; i++) {
        int idx = i * NTHREADS + tid;
        int e = idx >> 7;
        int j = idx & 127;
        int sw = j * 128 + (e ^ (j & 31));
        U[sw] = __ldg(&h[(long)ROW[e] * DDIM + j]);
        V[sw] = __ldg(&g[(long)TYP[e] * DDIM + j]);
    }

    // ---- accumulators: 8 edges x 8 dims per thread, packed as f32x2 along d
    unsigned long long acc[8][4];
#pragma unroll
    for (int i = 0; i < 8; i++)
#pragma unroll
        for (int p = 0; p < 4; p++) acc[i][p] = 0ull;

    // ---- K loop: 16 channels x 2 half-channels (Kc = 64) ----
    for (int c = 0; c < 16; c++) {
        const float a = CA[c], b = CB[c], dcoef = CD[c];
#pragma unroll 1
        for (int half = 0; half < 2; half++) {
            __syncthreads();   // protect F/W buffers from previous chunk's readers
            const int j0  = half * KC;
            const int kg0 = c * DDIM + j0;
            // fill feat chunk F[kl][e] and weight chunk W[kl][d]
#pragma unroll 4
            for (int i = 0; i < 32; i++) {
                int idx = i * NTHREADS + tid;
                int e  = idx & 127;
                int kl = idx >> 7;
                int j  = j0 + kl;
                int sw = j * 128 + (e ^ (j & 31));
                float f = fmaf(a, U[sw], fmaf(b, V[sw], dcoef));
                F[kl * 128 + e] = fmaxf(f, 0.0f);
                W[idx] = __ldg(&fc_w[(long)(kg0 + kl) * DDIM + e]);
            }
            __syncthreads();
            // register-blocked GEMM: acc[e][d] += F[k][e] * W[k][d]
#pragma unroll 4
            for (int k = 0; k < KC; k++) {
                const float4 fA = *reinterpret_cast<const float4*>(&F[k * 128 + (ty << 2)]);
                const float4 fB = *reinterpret_cast<const float4*>(&F[k * 128 + 64 + (ty << 2)]);
                const ulonglong2 wA = *reinterpret_cast<const ulonglong2*>(&W[k * 128 + (tx << 2)]);
                const ulonglong2 wB = *reinterpret_cast<const ulonglong2*>(&W[k * 128 + 64 + (tx << 2)]);
                unsigned long long fd[8];
                fd[0] = pack_dup(fA.x); fd[1] = pack_dup(fA.y);
                fd[2] = pack_dup(fA.z); fd[3] = pack_dup(fA.w);
                fd[4] = pack_dup(fB.x); fd[5] = pack_dup(fB.y);
                fd[6] = pack_dup(fB.z); fd[7] = pack_dup(fB.w);
                unsigned long long wp[4];
                wp[0] = wA.x; wp[1] = wA.y; wp[2] = wB.x; wp[3] = wB.y;
#pragma unroll
                for (int ei = 0; ei < 8; ei++)
#pragma unroll
                    for (int p = 0; p < 4; p++)
                        fma2(acc[ei][p], fd[ei], wp[p]);
            }
        }
    }

    // ---- epilogue: bn3 + relu + dot with object embedding h[col] ----
    float dot[8];
#pragma unroll
    for (int ei = 0; ei < 8; ei++) dot[ei] = 0.0f;

#pragma unroll
    for (int ei = 0; ei < 8; ei++) {
        const int e = (ei < 4) ? (ty * 4 + ei) : (64 + ty * 4 + (ei - 4));
        const long cbase = (long)COL[e] * DDIM;
#pragma unroll
        for (int p = 0; p < 4; p++) {
            const int d = (p < 2) ? ((tx << 2) + 2 * p) : (64 + (tx << 2) + 2 * (p - 2));
            float2 z = unpack2(acc[ei][p]);
            float z0 = fmaxf(fmaf(z.x, S3[d],     Q3[d]),     0.0f);
            float z1 = fmaxf(fmaf(z.y, S3[d + 1], Q3[d + 1]), 0.0f);
            float2 cj = __ldg(reinterpret_cast<const float2*>(&h[cbase + d]));
            dot[ei] = fmaf(z0, cj.x, fmaf(z1, cj.y, dot[ei]));
        }
    }

    // reduce over the 16 tx lanes that share (ty, e)
#pragma unroll
    for (int ei = 0; ei < 8; ei++) {
        float s = dot[ei];
        s += __shfl_down_sync(0xffffffffu, s, 8, 16);
        s += __shfl_down_sync(0xffffffffu, s, 4, 16);
        s += __shfl_down_sync(0xffffffffu, s, 2, 16);
        s += __shfl_down_sync(0xffffffffu, s, 1, 16);
        if (tx == 0) {
            const int e = (ei < 4) ? (ty * 4 + ei) : (64 + ty * 4 + (ei - 4));
            out[e0 + e] = s;
        }
    }
}

extern "C" void kernel_launch(void* const* d_in, const int* in_sizes, int n_in,
                              void* d_out, int out_size)
{
    const float* h      = (const float*)d_in[0];
    const float* g      = (const float*)d_in[1];
    const int*   eidx   = (const int*)d_in[2];
    const int*   etype  = (const int*)d_in[3];
    const float* conv_w = (const float*)d_in[4];
    const float* conv_b = (const float*)d_in[5];
    const float* fc_w   = (const float*)d_in[6];
    const float* fc_b   = (const float*)d_in[7];
    const float* bn1g   = (const float*)d_in[8];
    const float* bn1b   = (const float*)d_in[9];
    const float* bn1m   = (const float*)d_in[10];
    const float* bn1v   = (const float*)d_in[11];
    const float* bn3g   = (const float*)d_in[12];
    const float* bn3b   = (const float*)d_in[13];
    const float* bn3m   = (const float*)d_in[14];
    const float* bn3v   = (const float*)d_in[15];
    float* out = (float*)d_out;

    cudaFuncSetAttribute(conve_kernel,
                         cudaFuncAttributeMaxDynamicSharedMemorySize, SMEM_BYTES);
    conve_kernel<<<E_TOT / TILE_E, NTHREADS, SMEM_BYTES>>>(
        h, g, eidx, etype, conv_w, conv_b, fc_w, fc_b,
        bn1g, bn1b, bn1m, bn1v, bn3g, bn3b, bn3m, bn3v, out);
}

// round 3
// speedup vs baseline: 1.9881x; 1.9881x over previous
#include <cuda_runtime.h>
#include <cstdint>

#define E_TOT    131072
#define DDIM     128
#define KTOT     2048
#define TILE_E   128
#define NTHREADS 256
#define NCHUNKS  64
#define FSTRIDE  36     // floats per row in F/Bs tiles (32 + 4 pad)
#define USTRIDE  132    // floats per row in U/V tiles (128 + 4 pad)

// ---- SMEM byte offsets ----
#define F0_OFF   0                              // 128*36*4 = 18432
#define F1_OFF   18432
#define B0_OFF   36864
#define B1_OFF   55296
#define U_OFF    73728                          // 128*132*4 = 67584
#define V_OFF    141312
#define S3_OFF   208896                         // 128 f
#define Q3_OFF   209408
#define CA_OFF   209920                         // 16 f
#define CB_OFF   209984
#define CD_OFF   210048
#define ROW_OFF  210112                         // 128 i
#define COL_OFF  210624
#define TYP_OFF  211136
#define SMEM_BYTES 211712

// fc_w transposed, tf32-rounded, k-permuted: g_Bt[n][kst], kst = perm(k)
__device__ float g_Bt[DDIM * KTOT];

__device__ __forceinline__ float tf32r(float x) {
    uint32_t r;
    asm("cvt.rna.tf32.f32 %0, %1;" : "=r"(r) : "f"(x));
    return __uint_as_float(r);
}
__device__ __forceinline__ void mma_tf32(float* c, const uint32_t* a,
                                         uint32_t b0, uint32_t b1) {
    asm volatile(
        "mma.sync.aligned.m16n8k8.row.col.f32.tf32.tf32.f32 "
        "{%0,%1,%2,%3}, {%4,%5,%6,%7}, {%8,%9}, {%0,%1,%2,%3};"
        : "+f"(c[0]), "+f"(c[1]), "+f"(c[2]), "+f"(c[3])
        : "r"(a[0]), "r"(a[1]), "r"(a[2]), "r"(a[3]), "r"(b0), "r"(b1));
}

// ===== prep: g_Bt[n][perm(k)] = tf32(fc_w[k][n]) =====
extern "C" __global__ void conve_prep(const float* __restrict__ fc_w)
{
    __shared__ float t[32][33];
    const int kb = blockIdx.x * 32;
    const int nb = blockIdx.y * 32;
    const int tx = threadIdx.x & 31;
    const int ty = threadIdx.x >> 5;   // 0..7
#pragma unroll
    for (int i = 0; i < 32; i += 8)
        t[ty + i][tx] = fc_w[(long)(kb + ty + i) * DDIM + nb + tx];
    __syncthreads();
#pragma unroll
    for (int i = 0; i < 32; i += 8) {
        const int k = kb + tx;
        const int kst = (k & ~7) | ((k & 3) << 1) | ((k >> 2) & 1);
        g_Bt[(long)(nb + ty + i) * KTOT + kst] = tf32r(t[tx][ty + i]);
    }
}

// ===== main =====
extern "C" __global__ void __launch_bounds__(NTHREADS, 1)
conve_main(const float* __restrict__ h, const float* __restrict__ g,
           const int* __restrict__ eidx, const int* __restrict__ etype,
           const float* __restrict__ conv_w, const float* __restrict__ conv_b,
           const float* __restrict__ fc_b,
           const float* __restrict__ bn1g, const float* __restrict__ bn1b,
           const float* __restrict__ bn1m, const float* __restrict__ bn1v,
           const float* __restrict__ bn3g, const float* __restrict__ bn3b,
           const float* __restrict__ bn3m, const float* __restrict__ bn3v,
           float* __restrict__ out)
{
    extern __shared__ char smc[];
    float* U  = (float*)(smc + U_OFF);
    float* V  = (float*)(smc + V_OFF);
    float* S3 = (float*)(smc + S3_OFF);
    float* Q3 = (float*)(smc + Q3_OFF);
    float* CA = (float*)(smc + CA_OFF);
    float* CB = (float*)(smc + CB_OFF);
    float* CD = (float*)(smc + CD_OFF);
    int* ROW = (int*)(smc + ROW_OFF);
    int* COL = (int*)(smc + COL_OFF);
    int* TYP = (int*)(smc + TYP_OFF);

    const int tid  = threadIdx.x;
    const int wid  = tid >> 5;
    const int lane = tid & 31;
    const int gid  = lane >> 2;
    const int tig  = lane & 3;
    const int e0   = blockIdx.x * TILE_E;

    const int ebase = (wid & 3) * 32;    // warp m block
    const int nbase = (wid >> 2) * 64;   // warp n block

    if (tid < DDIM) {
        float s = bn3g[tid] * rsqrtf(bn3v[tid] + 1e-5f);
        S3[tid] = s;
        Q3[tid] = fc_b[tid] * s + bn3b[tid] - bn3m[tid] * s;
        ROW[tid] = eidx[e0 + tid];
        COL[tid] = eidx[E_TOT + e0 + tid];
        TYP[tid] = etype[e0 + tid];
    }
    if (tid < 16) {
        float s1 = bn1g[0] * rsqrtf(bn1v[0] + 1e-5f);
        float b1 = bn1b[0] - bn1m[0] * s1;
        float w0 = conv_w[tid * 2], w1 = conv_w[tid * 2 + 1];
        CA[tid] = w0 * s1;
        CB[tid] = w1 * s1;
        CD[tid] = (w0 + w1) * b1 + conv_b[tid];
    }
    __syncthreads();

    // gather h[row], g[type] -> U[e][j], V[e][j] (stride 132)
#pragma unroll 4
    for (int i = 0; i < 64; i++) {
        int idx = i * NTHREADS + tid;
        int e = idx >> 7;
        int j = idx & 127;
        U[e * USTRIDE + j] = __ldg(&h[(long)ROW[e] * DDIM + j]);
        V[e * USTRIDE + j] = __ldg(&g[(long)TYP[e] * DDIM + j]);
    }

    float acc[2][8][4];
#pragma unroll
    for (int mt = 0; mt < 2; mt++)
#pragma unroll
        for (int nt = 0; nt < 8; nt++)
#pragma unroll
            for (int q = 0; q < 4; q++) acc[mt][nt][q] = 0.0f;

    // build/stage indices (per thread): one row, 16 k per thread
    const int be  = tid >> 1;            // row (edge for F, n for Bs)
    const int bkh = (tid & 1) << 4;      // k half offset 0/16

    __syncthreads();

    for (int chunk = 0; chunk < NCHUNKS; chunk++) {
        const int buf = chunk & 1;
        float* F  = (float*)(smc + (buf ? F1_OFF : F0_OFF));
        float* Bs = (float*)(smc + (buf ? B1_OFF : B0_OFF));
        const int k0 = chunk * 32;
        const int c  = chunk >> 2;           // channel = k0/128
        const int j0 = (chunk & 3) * 32;     // j offset within channel
        const float ca = CA[c], cb = CB[c], cd = CD[c];

        // ---- build F[e][kst] = tf32(relu(ca*U + cb*V + cd)), k-permuted ----
        {
            const float* Ue = U + be * USTRIDE + j0 + bkh;
            const float* Ve = V + be * USTRIDE + j0 + bkh;
            float u[16], v[16];
#pragma unroll
            for (int q4 = 0; q4 < 4; q4++) {
                *(float4*)&u[q4 * 4] = *(const float4*)(Ue + q4 * 4);
                *(float4*)&v[q4 * 4] = *(const float4*)(Ve + q4 * 4);
            }
            float* Frow = F + be * FSTRIDE + bkh;
#pragma unroll
            for (int grp = 0; grp < 2; grp++) {
                float tmp[8];
#pragma unroll
                for (int p = 0; p < 8; p++) {
                    const int kk = grp * 8 + ((p & 1) * 4 + (p >> 1)); // logical k
                    float f = fmaf(ca, u[kk], fmaf(cb, v[kk], cd));
                    tmp[p] = tf32r(fmaxf(f, 0.0f));
                }
                *(float4*)(Frow + grp * 8)     = *(float4*)&tmp[0];
                *(float4*)(Frow + grp * 8 + 4) = *(float4*)&tmp[4];
            }
            // ---- stage Bs[n][kst] from pre-permuted g_Bt ----
            const float* Bg = g_Bt + (long)be * KTOT + k0 + bkh;
            float* Brow = Bs + be * FSTRIDE + bkh;
#pragma unroll
            for (int q4 = 0; q4 < 4; q4++)
                *(float4*)(Brow + q4 * 4) = __ldg((const float4*)(Bg + q4 * 4));
        }
        __syncthreads();

        // ---- mma phase: 4 k8-steps ----
#pragma unroll
        for (int ks = 0; ks < 32; ks += 8) {
            uint32_t a[2][4];
#pragma unroll
            for (int mt = 0; mt < 2; mt++) {
                const int r = ebase + mt * 16 + gid;
                const float2 fa = *(const float2*)&F[r * FSTRIDE + ks + 2 * tig];
                const float2 fb = *(const float2*)&F[(r + 8) * FSTRIDE + ks + 2 * tig];
                a[mt][0] = __float_as_uint(fa.x);
                a[mt][1] = __float_as_uint(fb.x);
                a[mt][2] = __float_as_uint(fa.y);
                a[mt][3] = __float_as_uint(fb.y);
            }
#pragma unroll
            for (int nt = 0; nt < 8; nt++) {
                const int n = nbase + nt * 8 + gid;
                const float2 bb = *(const float2*)&Bs[n * FSTRIDE + ks + 2 * tig];
                const uint32_t b0 = __float_as_uint(bb.x);
                const uint32_t b1 = __float_as_uint(bb.y);
                mma_tf32(acc[0][nt], a[0], b0, b1);
                mma_tf32(acc[1][nt], a[1], b0, b1);
            }
        }
    }
    __syncthreads();   // all mma done before reusing F0 as reduction scratch

    // ---- epilogue: bn3 + relu + dot(h[col]) ----
    long cbase[4];
#pragma unroll
    for (int rr = 0; rr < 4; rr++)
        cbase[rr] = (long)COL[ebase + (rr >> 1) * 16 + (rr & 1) * 8 + gid] * DDIM;

    float dotp[4] = {0.f, 0.f, 0.f, 0.f};
#pragma unroll
    for (int nt = 0; nt < 8; nt++) {
        const int n = nbase + nt * 8 + 2 * tig;
        const float2 s3 = *(const float2*)&S3[n];
        const float2 q3 = *(const float2*)&Q3[n];
#pragma unroll
        for (int mt = 0; mt < 2; mt++) {
#pragma unroll
            for (int hh = 0; hh < 2; hh++) {
                const int rr = mt * 2 + hh;
                float z0 = fmaxf(fmaf(acc[mt][nt][hh * 2 + 0], s3.x, q3.x), 0.0f);
                float z1 = fmaxf(fmaf(acc[mt][nt][hh * 2 + 1], s3.y, q3.y), 0.0f);
                const float2 c2 = __ldg((const float2*)(h + cbase[rr] + n));
                dotp[rr] = fmaf(z0, c2.x, fmaf(z1, c2.y, dotp[rr]));
            }
        }
    }

    float* dsum = (float*)(smc + F0_OFF);   // 256 floats scratch
#pragma unroll
    for (int rr = 0; rr < 4; rr++) {
        float s = dotp[rr];
        s += __shfl_xor_sync(0xffffffffu, s, 1, 4);
        s += __shfl_xor_sync(0xffffffffu, s, 2, 4);
        if (tig == 0) {
            const int e = ebase + (rr >> 1) * 16 + (rr & 1) * 8 + gid;
            dsum[(wid >> 2) * 128 + e] = s;
        }
    }
    __syncthreads();
    if (tid < 128) out[e0 + tid] = dsum[tid] + dsum[128 + tid];
}

// ===== launch =====
extern "C" void kernel_launch(void* const* d_in, const int* in_sizes, int n_in,
                              void* d_out, int out_size)
{
    const float* h      = (const float*)d_in[0];
    const float* g      = (const float*)d_in[1];
    const int*   eidx   = (const int*)d_in[2];
    const int*   etype  = (const int*)d_in[3];
    const float* conv_w = (const float*)d_in[4];
    const float* conv_b = (const float*)d_in[5];
    const float* fc_w   = (const float*)d_in[6];
    const float* fc_b   = (const float*)d_in[7];
    const float* bn1g   = (const float*)d_in[8];
    const float* bn1b   = (const float*)d_in[9];
    const float* bn1m   = (const float*)d_in[10];
    const float* bn1v   = (const float*)d_in[11];
    const float* bn3g   = (const float*)d_in[12];
    const float* bn3b   = (const float*)d_in[13];
    const float* bn3m   = (const float*)d_in[14];
    const float* bn3v   = (const float*)d_in[15];
    float* out = (float*)d_out;

    dim3 pgrid(KTOT / 32, DDIM / 32);
    conve_prep<<<pgrid, 256>>>(fc_w);

    cudaFuncSetAttribute(conve_main,
                         cudaFuncAttributeMaxDynamicSharedMemorySize, SMEM_BYTES);
    conve_main<<<E_TOT / TILE_E, NTHREADS, SMEM_BYTES>>>(
        h, g, eidx, etype, conv_w, conv_b, fc_b,
        bn1g, bn1b, bn1m, bn1v, bn3g, bn3b, bn3m, bn3v, out);
}

// round 4
// speedup vs baseline: 2.7064x; 1.3613x over previous
#include <cuda_runtime.h>
#include <cstdint>

#define E_TOT    131072
#define DDIM     128
#define KTOT     2048
#define TILE_E   128
#define NTHREADS 384
#define NCHUNKS  64
#define FSTRIDE  40     // floats per row in F/Bs tiles (32 + 8 pad, LDS.64-conflict-free)
#define USTRIDE  132    // floats per row in U/V tiles

// ---- SMEM byte offsets ----
#define F0_OFF   0                    // 128*40*4 = 20480
#define F1_OFF   20480
#define B0_OFF   40960
#define B1_OFF   61440
#define U_OFF    81920                // 128*132*4 = 67584
#define V_OFF    149504
#define S3_OFF   217088
#define Q3_OFF   217600
#define CA_OFF   218112
#define CB_OFF   218176
#define CD_OFF   218240
#define ROW_OFF  218304
#define COL_OFF  218816
#define TYP_OFF  219328
#define MB_OFF   219840               // full0, full1, empty0, empty1 (8B each)
#define SMEM_BYTES 219904

// fc_w transposed, tf32-rounded, k-permuted: g_Bt[n][kst]
__device__ float g_Bt[DDIM * KTOT];

__device__ __forceinline__ uint32_t smem_u32(const void* p) {
    uint32_t a;
    asm("{ .reg .u64 t; cvta.to.shared.u64 t, %1; cvt.u32.u64 %0, t; }"
        : "=r"(a) : "l"(p));
    return a;
}
__device__ __forceinline__ float tf32r(float x) {
    uint32_t r;
    asm("cvt.rna.tf32.f32 %0, %1;" : "=r"(r) : "f"(x));
    return __uint_as_float(r);
}
__device__ __forceinline__ void mma_tf32(float* c, const uint32_t* a,
                                         uint32_t b0, uint32_t b1) {
    asm volatile(
        "mma.sync.aligned.m16n8k8.row.col.f32.tf32.tf32.f32 "
        "{%0,%1,%2,%3}, {%4,%5,%6,%7}, {%8,%9}, {%0,%1,%2,%3};"
        : "+f"(c[0]), "+f"(c[1]), "+f"(c[2]), "+f"(c[3])
        : "r"(a[0]), "r"(a[1]), "r"(a[2]), "r"(a[3]), "r"(b0), "r"(b1));
}
__device__ __forceinline__ void mbar_init(uint32_t mb, uint32_t cnt) {
    asm volatile("mbarrier.init.shared.b64 [%0], %1;" :: "r"(mb), "r"(cnt) : "memory");
}
__device__ __forceinline__ void mbar_arrive(uint32_t mb) {
    asm volatile("mbarrier.arrive.shared.b64 _, [%0];" :: "r"(mb) : "memory");
}
__device__ __forceinline__ void mbar_wait(uint32_t mb, uint32_t parity) {
    asm volatile(
        "{\n\t"
        ".reg .pred P;\n\t"
        "LAB_W%=:\n\t"
        "mbarrier.try_wait.parity.acquire.cta.shared::cta.b64 P, [%0], %1, 0x989680;\n\t"
        "@P bra.uni LAB_D%=;\n\t"
        "bra.uni LAB_W%=;\n\t"
        "LAB_D%=:\n\t"
        "}"
        :: "r"(mb), "r"(parity) : "memory");
}

// ===== prep: g_Bt[n][perm(k)] = tf32(fc_w[k][n]) =====
extern "C" __global__ void conve_prep(const float* __restrict__ fc_w)
{
    __shared__ float t[32][33];
    const int kb = blockIdx.x * 32;
    const int nb = blockIdx.y * 32;
    const int tx = threadIdx.x & 31;
    const int ty = threadIdx.x >> 5;
#pragma unroll
    for (int i = 0; i < 32; i += 8)
        t[ty + i][tx] = fc_w[(long)(kb + ty + i) * DDIM + nb + tx];
    __syncthreads();
#pragma unroll
    for (int i = 0; i < 32; i += 8) {
        const int k = kb + tx;
        const int kst = (k & ~7) | ((k & 3) << 1) | ((k >> 2) & 1);
        g_Bt[(long)(nb + ty + i) * KTOT + kst] = tf32r(t[tx][ty + i]);
    }
}

// ===== main: warp-specialized producer/consumer =====
extern "C" __global__ void __launch_bounds__(NTHREADS, 1)
conve_main(const float* __restrict__ h, const float* __restrict__ g,
           const int* __restrict__ eidx, const int* __restrict__ etype,
           const float* __restrict__ conv_w, const float* __restrict__ conv_b,
           const float* __restrict__ fc_b,
           const float* __restrict__ bn1g, const float* __restrict__ bn1b,
           const float* __restrict__ bn1m, const float* __restrict__ bn1v,
           const float* __restrict__ bn3g, const float* __restrict__ bn3b,
           const float* __restrict__ bn3m, const float* __restrict__ bn3v,
           float* __restrict__ out)
{
    extern __shared__ char smc[];
    float* U  = (float*)(smc + U_OFF);
    float* V  = (float*)(smc + V_OFF);
    float* S3 = (float*)(smc + S3_OFF);
    float* Q3 = (float*)(smc + Q3_OFF);
    float* CA = (float*)(smc + CA_OFF);
    float* CB = (float*)(smc + CB_OFF);
    float* CD = (float*)(smc + CD_OFF);
    int* ROW = (int*)(smc + ROW_OFF);
    int* COL = (int*)(smc + COL_OFF);
    int* TYP = (int*)(smc + TYP_OFF);

    const uint32_t smem_base = smem_u32(smc);
    const uint32_t full0  = smem_base + MB_OFF;
    const uint32_t full1  = smem_base + MB_OFF + 8;
    const uint32_t empty0 = smem_base + MB_OFF + 16;
    const uint32_t empty1 = smem_base + MB_OFF + 24;

    const int tid  = threadIdx.x;
    const int e0   = blockIdx.x * TILE_E;

    if (tid == 0) {
        mbar_init(full0, 128);   // producers arrive per-thread
        mbar_init(full1, 128);
        mbar_init(empty0, 256);  // consumers arrive per-thread
        mbar_init(empty1, 256);
    }
    if (tid < DDIM) {
        float s = bn3g[tid] * rsqrtf(bn3v[tid] + 1e-5f);
        S3[tid] = s;
        Q3[tid] = fc_b[tid] * s + bn3b[tid] - bn3m[tid] * s;
        ROW[tid] = eidx[e0 + tid];
        COL[tid] = eidx[E_TOT + e0 + tid];
        TYP[tid] = etype[e0 + tid];
    }
    if (tid < 16) {
        float s1 = bn1g[0] * rsqrtf(bn1v[0] + 1e-5f);
        float b1 = bn1b[0] - bn1m[0] * s1;
        float w0 = conv_w[tid * 2], w1 = conv_w[tid * 2 + 1];
        CA[tid] = w0 * s1;
        CB[tid] = w1 * s1;
        CD[tid] = (w0 + w1) * b1 + conv_b[tid];
    }
    __syncthreads();

    // ---- gather h[row], g[type] -> U[e][j], V[e][j] (all 384 threads) ----
    for (int idx = tid; idx < TILE_E * DDIM; idx += NTHREADS) {
        const int e = idx >> 7;
        const int j = idx & 127;
        U[e * USTRIDE + j] = __ldg(&h[(long)ROW[e] * DDIM + j]);
        V[e * USTRIDE + j] = __ldg(&g[(long)TYP[e] * DDIM + j]);
    }
    __syncthreads();

    if (tid >= 256) {
        // ================= PRODUCER (warps 8-11) =================
        const int ptid = tid - 256;          // 0..127
        const int bn_row0 = ptid >> 3;       // base n row for B staging
        const int bn_kq   = ptid & 7;        // 16B k segment
        int pph[2] = {1, 1};

        for (int chunk = 0; chunk < NCHUNKS; chunk++) {
            const int buf = chunk & 1;
            const int k0  = chunk * 32;
            const int c   = chunk >> 2;
            const int j0  = (chunk & 3) * 32;
            const float ca = CA[c], cb = CB[c], cd = CD[c];

            // -- pre-wait work: LDG B chunk + compute feat into regs --
            float4 breg[8];
#pragma unroll
            for (int i = 0; i < 8; i++) {
                const int n = bn_row0 + i * 16;
                breg[i] = __ldg((const float4*)&g_Bt[(long)n * KTOT + k0 + bn_kq * 4]);
            }
            float u[32], v[32], fr[32];
            const float* Ue = U + ptid * USTRIDE + j0;
            const float* Ve = V + ptid * USTRIDE + j0;
#pragma unroll
            for (int q4 = 0; q4 < 8; q4++) {
                *(float4*)&u[q4 * 4] = *(const float4*)(Ue + q4 * 4);
                *(float4*)&v[q4 * 4] = *(const float4*)(Ve + q4 * 4);
            }
#pragma unroll
            for (int grp = 0; grp < 4; grp++) {
#pragma unroll
                for (int p = 0; p < 8; p++) {
                    const int kk = grp * 8 + ((p & 1) * 4 + (p >> 1));
                    float f = fmaf(ca, u[kk], fmaf(cb, v[kk], cd));
                    fr[grp * 8 + p] = tf32r(fmaxf(f, 0.0f));
                }
            }

            // -- acquire buffer, store, publish --
            mbar_wait(buf ? empty1 : empty0, pph[buf]);
            pph[buf] ^= 1;

            float* F  = (float*)(smc + (buf ? F1_OFF : F0_OFF));
            float* Bs = (float*)(smc + (buf ? B1_OFF : B0_OFF));
            float* Frow = F + ptid * FSTRIDE;
#pragma unroll
            for (int q4 = 0; q4 < 8; q4++)
                *(float4*)(Frow + q4 * 4) = *(float4*)&fr[q4 * 4];
#pragma unroll
            for (int i = 0; i < 8; i++) {
                const int n = bn_row0 + i * 16;
                *(float4*)(Bs + n * FSTRIDE + bn_kq * 4) = breg[i];
            }
            mbar_arrive(buf ? full1 : full0);
        }
    } else {
        // ================= CONSUMER (warps 0-7) =================
        const int wid  = tid >> 5;
        const int lane = tid & 31;
        const int gid  = lane >> 2;
        const int tig  = lane & 3;
        const int ebase = (wid & 3) * 32;
        const int nbase = (wid >> 2) * 64;

        float acc[2][8][4];
#pragma unroll
        for (int mt = 0; mt < 2; mt++)
#pragma unroll
            for (int nt = 0; nt < 8; nt++)
#pragma unroll
                for (int q = 0; q < 4; q++) acc[mt][nt][q] = 0.0f;

        int cph[2] = {0, 0};
        for (int chunk = 0; chunk < NCHUNKS; chunk++) {
            const int buf = chunk & 1;
            mbar_wait(buf ? full1 : full0, cph[buf]);
            cph[buf] ^= 1;

            const float* F  = (const float*)(smc + (buf ? F1_OFF : F0_OFF));
            const float* Bs = (const float*)(smc + (buf ? B1_OFF : B0_OFF));
#pragma unroll
            for (int ks = 0; ks < 32; ks += 8) {
                uint32_t a[2][4];
#pragma unroll
                for (int mt = 0; mt < 2; mt++) {
                    const int r = ebase + mt * 16 + gid;
                    const float2 fa = *(const float2*)&F[r * FSTRIDE + ks + 2 * tig];
                    const float2 fb = *(const float2*)&F[(r + 8) * FSTRIDE + ks + 2 * tig];
                    a[mt][0] = __float_as_uint(fa.x);
                    a[mt][1] = __float_as_uint(fb.x);
                    a[mt][2] = __float_as_uint(fa.y);
                    a[mt][3] = __float_as_uint(fb.y);
                }
#pragma unroll
                for (int nt = 0; nt < 8; nt++) {
                    const int n = nbase + nt * 8 + gid;
                    const float2 bb = *(const float2*)&Bs[n * FSTRIDE + ks + 2 * tig];
                    const uint32_t b0 = __float_as_uint(bb.x);
                    const uint32_t b1 = __float_as_uint(bb.y);
                    mma_tf32(acc[0][nt], a[0], b0, b1);
                    mma_tf32(acc[1][nt], a[1], b0, b1);
                }
            }
            mbar_arrive(buf ? empty1 : empty0);
        }

        // ---- epilogue: bn3 + relu + dot(h[col]) ----
        long cbase[4];
#pragma unroll
        for (int rr = 0; rr < 4; rr++)
            cbase[rr] = (long)COL[ebase + (rr >> 1) * 16 + (rr & 1) * 8 + gid] * DDIM;

        float dotp[4] = {0.f, 0.f, 0.f, 0.f};
#pragma unroll
        for (int nt = 0; nt < 8; nt++) {
            const int n = nbase + nt * 8 + 2 * tig;
            const float2 s3 = *(const float2*)&S3[n];
            const float2 q3 = *(const float2*)&Q3[n];
#pragma unroll
            for (int mt = 0; mt < 2; mt++) {
#pragma unroll
                for (int hh = 0; hh < 2; hh++) {
                    const int rr = mt * 2 + hh;
                    float z0 = fmaxf(fmaf(acc[mt][nt][hh * 2 + 0], s3.x, q3.x), 0.0f);
                    float z1 = fmaxf(fmaf(acc[mt][nt][hh * 2 + 1], s3.y, q3.y), 0.0f);
                    const float2 c2 = __ldg((const float2*)(h + cbase[rr] + n));
                    dotp[rr] = fmaf(z0, c2.x, fmaf(z1, c2.y, dotp[rr]));
                }
            }
        }

        float* dsum = (float*)(smc + F0_OFF);
        __syncwarp();
#pragma unroll
        for (int rr = 0; rr < 4; rr++) {
            float s = dotp[rr];
            s += __shfl_xor_sync(0xffffffffu, s, 1, 4);
            s += __shfl_xor_sync(0xffffffffu, s, 2, 4);
            if (tig == 0) {
                const int e = ebase + (rr >> 1) * 16 + (rr & 1) * 8 + gid;
                dsum[(wid >> 2) * 128 + e] = s;
            }
        }
    }

    __syncthreads();   // join producers + consumers; dsum visible
    if (tid < 128) {
        float* dsum = (float*)(smc + F0_OFF);
        out[e0 + tid] = dsum[tid] + dsum[128 + tid];
    }
}

// ===== launch =====
extern "C" void kernel_launch(void* const* d_in, const int* in_sizes, int n_in,
                              void* d_out, int out_size)
{
    const float* h      = (const float*)d_in[0];
    const float* g      = (const float*)d_in[1];
    const int*   eidx   = (const int*)d_in[2];
    const int*   etype  = (const int*)d_in[3];
    const float* conv_w = (const float*)d_in[4];
    const float* conv_b = (const float*)d_in[5];
    const float* fc_w   = (const float*)d_in[6];
    const float* fc_b   = (const float*)d_in[7];
    const float* bn1g   = (const float*)d_in[8];
    const float* bn1b   = (const float*)d_in[9];
    const float* bn1m   = (const float*)d_in[10];
    const float* bn1v   = (const float*)d_in[11];
    const float* bn3g   = (const float*)d_in[12];
    const float* bn3b   = (const float*)d_in[13];
    const float* bn3m   = (const float*)d_in[14];
    const float* bn3v   = (const float*)d_in[15];
    float* out = (float*)d_out;

    dim3 pgrid(KTOT / 32, DDIM / 32);
    conve_prep<<<pgrid, 256>>>(fc_w);

    cudaFuncSetAttribute(conve_main,
                         cudaFuncAttributeMaxDynamicSharedMemorySize, SMEM_BYTES);
    conve_main<<<E_TOT / TILE_E, NTHREADS, SMEM_BYTES>>>(
        h, g, eidx, etype, conv_w, conv_b, fc_b,
        bn1g, bn1b, bn1m, bn1v, bn3g, bn3b, bn3m, bn3v, out);
}

// round 5
// speedup vs baseline: 2.8013x; 1.0350x over previous
#include <cuda_runtime.h>
#include <cstdint>

#define E_TOT    131072
#define DDIM     128
#define KTOT     2048
#define TILE_E   128
#define NTHREADS 640          // 512 consumer + 128 producer
#define NCHUNKS  64
#define FSTRIDE  40           // floats per F/B row (32 + 8 pad): consumer LDS.64 conflict-free
#define USTRIDE  129          // floats per U/V row: conflict-free scalar reads

// ---- SMEM byte offsets ----
#define F0_OFF   0            // 128*40*4 = 20480
#define F1_OFF   20480
#define B0_OFF   40960
#define B1_OFF   61440
#define U_OFF    81920        // 128*129*4 = 66048
#define V_OFF    147968
#define S3_OFF   214016       // 128 f
#define Q3_OFF   214528
#define CA_OFF   215040       // 16 f
#define CB_OFF   215104
#define CD_OFF   215168
#define ROW_OFF  215232       // 128 i
#define COL_OFF  215744
#define TYP_OFF  216256
#define DS_OFF   216768       // dsum: 4*128 floats = 2048B (dedicated, no race)
#define MB_OFF   218816       // full0, full1, empty0, empty1
#define SMEM_BYTES 218880

// fc_w, transposed + tf32-rounded + (j-major, mma-permuted) k order: g_Bt[n][kst]
__device__ float g_Bt[DDIM * KTOT];

__device__ __forceinline__ uint32_t smem_u32(const void* p) {
    uint32_t a;
    asm("{ .reg .u64 t; cvta.to.shared.u64 t, %1; cvt.u32.u64 %0, t; }"
        : "=r"(a) : "l"(p));
    return a;
}
__device__ __forceinline__ float tf32r(float x) {
    uint32_t r;
    asm("cvt.rna.tf32.f32 %0, %1;" : "=r"(r) : "f"(x));
    return __uint_as_float(r);
}
__device__ __forceinline__ void mma_tf32(float* c, const uint32_t* a,
                                         uint32_t b0, uint32_t b1) {
    asm volatile(
        "mma.sync.aligned.m16n8k8.row.col.f32.tf32.tf32.f32 "
        "{%0,%1,%2,%3}, {%4,%5,%6,%7}, {%8,%9}, {%0,%1,%2,%3};"
        : "+f"(c[0]), "+f"(c[1]), "+f"(c[2]), "+f"(c[3])
        : "r"(a[0]), "r"(a[1]), "r"(a[2]), "r"(a[3]), "r"(b0), "r"(b1));
}
__device__ __forceinline__ void mbar_init(uint32_t mb, uint32_t cnt) {
    asm volatile("mbarrier.init.shared.b64 [%0], %1;" :: "r"(mb), "r"(cnt) : "memory");
}
__device__ __forceinline__ void mbar_arrive(uint32_t mb) {
    asm volatile("mbarrier.arrive.shared.b64 _, [%0];" :: "r"(mb) : "memory");
}
__device__ __forceinline__ void mbar_wait(uint32_t mb, uint32_t parity) {
    asm volatile(
        "{\n\t"
        ".reg .pred P;\n\t"
        "LAB_W%=:\n\t"
        "mbarrier.try_wait.parity.acquire.cta.shared::cta.b64 P, [%0], %1, 0x989680;\n\t"
        "@P bra.uni LAB_D%=;\n\t"
        "bra.uni LAB_W%=;\n\t"
        "LAB_D%=:\n\t"
        "}"
        :: "r"(mb), "r"(parity) : "memory");
}

// ===== prep: g_Bt[n][kst(k_log)] = tf32(fc_w[k_log][n]) =====
// k' = j*16 + c  (j-major);  kst = mma within-8 permutation of k'
extern "C" __global__ void conve_prep(const float* __restrict__ fc_w)
{
    __shared__ float t[32][33];
    const int kb = blockIdx.x * 32;
    const int nb = blockIdx.y * 32;
    const int tx = threadIdx.x & 31;
    const int ty = threadIdx.x >> 5;
#pragma unroll
    for (int i = 0; i < 32; i += 8)
        t[ty + i][tx] = fc_w[(long)(kb + ty + i) * DDIM + nb + tx];
    __syncthreads();
#pragma unroll
    for (int i = 0; i < 32; i += 8) {
        const int klog = kb + tx;
        const int c = klog >> 7;
        const int j = klog & 127;
        const int kp = j * 16 + c;
        const int kst = (kp & ~7) | ((kp & 3) << 1) | ((kp >> 2) & 1);
        g_Bt[(long)(nb + ty + i) * KTOT + kst] = tf32r(t[tx][ty + i]);
    }
}

// ===== main: warp-specialized, 16 consumer warps (4m x 4n), 4 producer warps =====
extern "C" __global__ void __launch_bounds__(NTHREADS, 1)
conve_main(const float* __restrict__ h, const float* __restrict__ g,
           const int* __restrict__ eidx, const int* __restrict__ etype,
           const float* __restrict__ conv_w, const float* __restrict__ conv_b,
           const float* __restrict__ fc_b,
           const float* __restrict__ bn1g, const float* __restrict__ bn1b,
           const float* __restrict__ bn1m, const float* __restrict__ bn1v,
           const float* __restrict__ bn3g, const float* __restrict__ bn3b,
           const float* __restrict__ bn3m, const float* __restrict__ bn3v,
           float* __restrict__ out)
{
    extern __shared__ char smc[];
    float* U  = (float*)(smc + U_OFF);
    float* V  = (float*)(smc + V_OFF);
    float* S3 = (float*)(smc + S3_OFF);
    float* Q3 = (float*)(smc + Q3_OFF);
    float* CA = (float*)(smc + CA_OFF);
    float* CB = (float*)(smc + CB_OFF);
    float* CD = (float*)(smc + CD_OFF);
    int* ROW = (int*)(smc + ROW_OFF);
    int* COL = (int*)(smc + COL_OFF);
    int* TYP = (int*)(smc + TYP_OFF);

    const uint32_t smem_base = smem_u32(smc);
    const uint32_t full0  = smem_base + MB_OFF;
    const uint32_t full1  = smem_base + MB_OFF + 8;
    const uint32_t empty0 = smem_base + MB_OFF + 16;
    const uint32_t empty1 = smem_base + MB_OFF + 24;

    const int tid = threadIdx.x;
    const int e0  = blockIdx.x * TILE_E;

    if (tid == 0) {
        mbar_init(full0, 128);    // producer threads arrive
        mbar_init(full1, 128);
        mbar_init(empty0, 512);   // consumer threads arrive
        mbar_init(empty1, 512);
    }
    if (tid < DDIM) {
        float s = bn3g[tid] * rsqrtf(bn3v[tid] + 1e-5f);
        S3[tid] = s;
        Q3[tid] = fc_b[tid] * s + bn3b[tid] - bn3m[tid] * s;
        ROW[tid] = eidx[e0 + tid];
        COL[tid] = eidx[E_TOT + e0 + tid];
        TYP[tid] = etype[e0 + tid];
    }
    if (tid < 16) {
        float s1 = bn1g[0] * rsqrtf(bn1v[0] + 1e-5f);
        float b1 = bn1b[0] - bn1m[0] * s1;
        float w0 = conv_w[tid * 2], w1 = conv_w[tid * 2 + 1];
        CA[tid] = w0 * s1;
        CB[tid] = w1 * s1;
        CD[tid] = (w0 + w1) * b1 + conv_b[tid];
    }
    __syncthreads();

    // ---- gather h[row], g[type] -> U[e][j], V[e][j] ----
    for (int idx = tid; idx < TILE_E * DDIM; idx += NTHREADS) {
        const int e = idx >> 7;
        const int j = idx & 127;
        U[e * USTRIDE + j] = __ldg(&h[(long)ROW[e] * DDIM + j]);
        V[e * USTRIDE + j] = __ldg(&g[(long)TYP[e] * DDIM + j]);
    }
    __syncthreads();

    if (tid >= 512) {
        // ================= PRODUCER (warps 16-19) =================
        const int ptid = tid - 512;       // 0..127
        const int pw   = ptid >> 5;       // producer warp 0..3
        const int pl   = ptid & 31;
        const int prsub = pl >> 3;        // row-within-pass 0..3
        const int pseg  = pl & 7;         // 16B k segment 0..7

        // lane-constant: stored index -> (channel, j-select, coeffs), hoisted
        float caq[4], cbq[4], cdq[4];
        int   jsel[4];
#pragma unroll
        for (int q = 0; q < 4; q++) {
            const int st = pseg * 4 + q;
            const int kl = (st & ~7) | ((st >> 1) & 3) | ((st & 1) << 2);
            const int c  = kl & 15;
            jsel[q] = kl >> 4;
            caq[q] = CA[c]; cbq[q] = CB[c]; cdq[q] = CD[c];
        }

        int pph[2] = {1, 1};
        for (int chunk = 0; chunk < NCHUNKS; chunk++) {
            const int buf = chunk & 1;
            const int k0  = chunk * 32;
            const int j0  = chunk * 2;

            // prefetch B (L2) before acquiring the buffer
            float4 breg[8];
#pragma unroll
            for (int p = 0; p < 8; p++) {
                const int row = pw * 32 + p * 4 + prsub;
                breg[p] = __ldg((const float4*)&g_Bt[(long)row * KTOT + k0 + pseg * 4]);
            }

            mbar_wait(buf ? empty1 : empty0, pph[buf]);
            pph[buf] ^= 1;

            float* F  = (float*)(smc + (buf ? F1_OFF : F0_OFF));
            float* Bs = (float*)(smc + (buf ? B1_OFF : B0_OFF));
#pragma unroll
            for (int p = 0; p < 8; p++) {
                const int row = pw * 32 + p * 4 + prsub;
                const float u0 = U[row * USTRIDE + j0];
                const float u1 = U[row * USTRIDE + j0 + 1];
                const float v0 = V[row * USTRIDE + j0];
                const float v1 = V[row * USTRIDE + j0 + 1];
                float fr[4];
#pragma unroll
                for (int q = 0; q < 4; q++) {
                    const float uu = jsel[q] ? u1 : u0;
                    const float vv = jsel[q] ? v1 : v0;
                    float f = fmaf(caq[q], uu, fmaf(cbq[q], vv, cdq[q]));
                    fr[q] = tf32r(fmaxf(f, 0.0f));
                }
                *(float4*)&F[row * FSTRIDE + pseg * 4] =
                    make_float4(fr[0], fr[1], fr[2], fr[3]);
                *(float4*)&Bs[row * FSTRIDE + pseg * 4] = breg[p];
            }
            mbar_arrive(buf ? full1 : full0);
        }
    } else {
        // ================= CONSUMER (warps 0-15, 4m x 4n) =================
        const int wid  = tid >> 5;
        const int lane = tid & 31;
        const int gid  = lane >> 2;
        const int tig  = lane & 3;
        const int ebase = (wid & 3) * 32;
        const int nbase = (wid >> 2) * 32;

        float acc[2][4][4];
#pragma unroll
        for (int mt = 0; mt < 2; mt++)
#pragma unroll
            for (int nt = 0; nt < 4; nt++)
#pragma unroll
                for (int q = 0; q < 4; q++) acc[mt][nt][q] = 0.0f;

        int cph[2] = {0, 0};
        for (int chunk = 0; chunk < NCHUNKS; chunk++) {
            const int buf = chunk & 1;
            mbar_wait(buf ? full1 : full0, cph[buf]);
            cph[buf] ^= 1;

            const float* F  = (const float*)(smc + (buf ? F1_OFF : F0_OFF));
            const float* Bs = (const float*)(smc + (buf ? B1_OFF : B0_OFF));
#pragma unroll
            for (int ks = 0; ks < 32; ks += 8) {
                uint32_t a[2][4];
#pragma unroll
                for (int mt = 0; mt < 2; mt++) {
                    const int r = ebase + mt * 16 + gid;
                    const float2 fa = *(const float2*)&F[r * FSTRIDE + ks + 2 * tig];
                    const float2 fb = *(const float2*)&F[(r + 8) * FSTRIDE + ks + 2 * tig];
                    a[mt][0] = __float_as_uint(fa.x);
                    a[mt][1] = __float_as_uint(fb.x);
                    a[mt][2] = __float_as_uint(fa.y);
                    a[mt][3] = __float_as_uint(fb.y);
                }
#pragma unroll
                for (int nt = 0; nt < 4; nt++) {
                    const int n = nbase + nt * 8 + gid;
                    const float2 bb = *(const float2*)&Bs[n * FSTRIDE + ks + 2 * tig];
                    const uint32_t b0 = __float_as_uint(bb.x);
                    const uint32_t b1 = __float_as_uint(bb.y);
                    mma_tf32(acc[0][nt], a[0], b0, b1);
                    mma_tf32(acc[1][nt], a[1], b0, b1);
                }
            }
            mbar_arrive(buf ? empty1 : empty0);
        }

        // ---- epilogue: bn3 + relu + dot(h[col]) over this warp's 32-col slice ----
        long cbase[4];
#pragma unroll
        for (int rr = 0; rr < 4; rr++) {
            const int e = ebase + (rr >> 1) * 16 + (rr & 1) * 8 + gid;
            cbase[rr] = (long)COL[e] * DDIM;
        }
        float dotp[4] = {0.f, 0.f, 0.f, 0.f};
#pragma unroll
        for (int nt = 0; nt < 4; nt++) {
            const int n = nbase + nt * 8 + 2 * tig;
            const float2 s3 = *(const float2*)&S3[n];
            const float2 q3 = *(const float2*)&Q3[n];
#pragma unroll
            for (int mt = 0; mt < 2; mt++) {
#pragma unroll
                for (int hh = 0; hh < 2; hh++) {
                    const int rr = mt * 2 + hh;
                    float z0 = fmaxf(fmaf(acc[mt][nt][hh * 2 + 0], s3.x, q3.x), 0.0f);
                    float z1 = fmaxf(fmaf(acc[mt][nt][hh * 2 + 1], s3.y, q3.y), 0.0f);
                    const float2 c2 = __ldg((const float2*)(h + cbase[rr] + n));
                    dotp[rr] = fmaf(z0, c2.x, fmaf(z1, c2.y, dotp[rr]));
                }
            }
        }

        float* dsum = (float*)(smc + DS_OFF);
#pragma unroll
        for (int rr = 0; rr < 4; rr++) {
            float s = dotp[rr];
            s += __shfl_xor_sync(0xffffffffu, s, 1, 4);
            s += __shfl_xor_sync(0xffffffffu, s, 2, 4);
            if (tig == 0) {
                const int e = ebase + (rr >> 1) * 16 + (rr & 1) * 8 + gid;
                dsum[(wid >> 2) * 128 + e] = s;
            }
        }
    }

    __syncthreads();   // join producers + consumers; dsum visible
    if (tid < 128) {
        const float* ds = (const float*)(smc + DS_OFF);
        out[e0 + tid] = (ds[tid] + ds[128 + tid]) + (ds[256 + tid] + ds[384 + tid]);
    }
}

// ===== launch =====
extern "C" void kernel_launch(void* const* d_in, const int* in_sizes, int n_in,
                              void* d_out, int out_size)
{
    const float* h      = (const float*)d_in[0];
    const float* g      = (const float*)d_in[1];
    const int*   eidx   = (const int*)d_in[2];
    const int*   etype  = (const int*)d_in[3];
    const float* conv_w = (const float*)d_in[4];
    const float* conv_b = (const float*)d_in[5];
    const float* fc_w   = (const float*)d_in[6];
    const float* fc_b   = (const float*)d_in[7];
    const float* bn1g   = (const float*)d_in[8];
    const float* bn1b   = (const float*)d_in[9];
    const float* bn1m   = (const float*)d_in[10];
    const float* bn1v   = (const float*)d_in[11];
    const float* bn3g   = (const float*)d_in[12];
    const float* bn3b   = (const float*)d_in[13];
    const float* bn3m   = (const float*)d_in[14];
    const float* bn3v   = (const float*)d_in[15];
    float* out = (float*)d_out;

    dim3 pgrid(KTOT / 32, DDIM / 32);
    conve_prep<<<pgrid, 256>>>(fc_w);

    cudaFuncSetAttribute(conve_main,
                         cudaFuncAttributeMaxDynamicSharedMemorySize, SMEM_BYTES);
    conve_main<<<E_TOT / TILE_E, NTHREADS, SMEM_BYTES>>>(
        h, g, eidx, etype, conv_w, conv_b, fc_b,
        bn1g, bn1b, bn1m, bn1v, bn3g, bn3b, bn3m, bn3v, out);
}

// round 6
// speedup vs baseline: 2.9795x; 1.0636x over previous
#include <cuda_runtime.h>
#include <cstdint>

#define E_TOT    131072
#define DDIM     128
#define KTOT     2048
#define TILE_E   64
#define NTHREADS 320          // 256 consumer + 64 producer
#define NCHUNKS  64
#define FSTRIDE  40           // floats per F/B row (32 + 8 pad)

// ---- SMEM byte offsets ----
#define F0_OFF   0            // 64*40*4  = 10240
#define F1_OFF   10240
#define B0_OFF   20480        // 128*40*4 = 20480
#define B1_OFF   40960
#define S3_OFF   61440        // 128 f
#define Q3_OFF   61952
#define CA_OFF   62464        // 16 f
#define CB_OFF   62528
#define CD_OFF   62592
#define ROW_OFF  62656        // 64 i
#define COL_OFF  62912
#define TYP_OFF  63168
#define DS_OFF   63424        // dsum: 4 quads * 64 e = 1024 B
#define MB_OFF   64448        // full0, full1, empty0, empty1
#define SMEM_BYTES 64512

// fc_w, transposed + tf32-rounded + (j-major, mma-permuted) k order: g_Bt[n][kst]
__device__ float g_Bt[DDIM * KTOT];

__device__ __forceinline__ uint32_t smem_u32(const void* p) {
    uint32_t a;
    asm("{ .reg .u64 t; cvta.to.shared.u64 t, %1; cvt.u32.u64 %0, t; }"
        : "=r"(a) : "l"(p));
    return a;
}
__device__ __forceinline__ float tf32r(float x) {
    uint32_t r;
    asm("cvt.rna.tf32.f32 %0, %1;" : "=r"(r) : "f"(x));
    return __uint_as_float(r);
}
__device__ __forceinline__ void mma_tf32(float* c, const uint32_t* a,
                                         uint32_t b0, uint32_t b1) {
    asm volatile(
        "mma.sync.aligned.m16n8k8.row.col.f32.tf32.tf32.f32 "
        "{%0,%1,%2,%3}, {%4,%5,%6,%7}, {%8,%9}, {%0,%1,%2,%3};"
        : "+f"(c[0]), "+f"(c[1]), "+f"(c[2]), "+f"(c[3])
        : "r"(a[0]), "r"(a[1]), "r"(a[2]), "r"(a[3]), "r"(b0), "r"(b1));
}
__device__ __forceinline__ void mbar_init(uint32_t mb, uint32_t cnt) {
    asm volatile("mbarrier.init.shared.b64 [%0], %1;" :: "r"(mb), "r"(cnt) : "memory");
}
__device__ __forceinline__ void mbar_arrive(uint32_t mb) {
    asm volatile("mbarrier.arrive.shared.b64 _, [%0];" :: "r"(mb) : "memory");
}
__device__ __forceinline__ void mbar_wait(uint32_t mb, uint32_t parity) {
    asm volatile(
        "{\n\t"
        ".reg .pred P;\n\t"
        "LAB_W%=:\n\t"
        "mbarrier.try_wait.parity.acquire.cta.shared::cta.b64 P, [%0], %1, 0x989680;\n\t"
        "@P bra.uni LAB_D%=;\n\t"
        "bra.uni LAB_W%=;\n\t"
        "LAB_D%=:\n\t"
        "}"
        :: "r"(mb), "r"(parity) : "memory");
}

// ===== prep: g_Bt[n][kst(k_log)] = tf32(fc_w[k_log][n]) =====
// k' = j*16 + c  (j-major);  kst = mma within-8 permutation of k'
extern "C" __global__ void conve_prep(const float* __restrict__ fc_w)
{
    __shared__ float t[32][33];
    const int kb = blockIdx.x * 32;
    const int nb = blockIdx.y * 32;
    const int tx = threadIdx.x & 31;
    const int ty = threadIdx.x >> 5;
#pragma unroll
    for (int i = 0; i < 32; i += 8)
        t[ty + i][tx] = fc_w[(long)(kb + ty + i) * DDIM + nb + tx];
    __syncthreads();
#pragma unroll
    for (int i = 0; i < 32; i += 8) {
        const int klog = kb + tx;
        const int c = klog >> 7;
        const int j = klog & 127;
        const int kp = j * 16 + c;
        const int kst = (kp & ~7) | ((kp & 3) << 1) | ((kp >> 2) & 1);
        g_Bt[(long)(nb + ty + i) * KTOT + kst] = tf32r(t[tx][ty + i]);
    }
}

// ===== main: 2 CTAs/SM, warp-specialized, 8 consumer (2m x 4n) + 2 producer =====
extern "C" __global__ void __launch_bounds__(NTHREADS, 2)
conve_main(const float* __restrict__ h, const float* __restrict__ g,
           const int* __restrict__ eidx, const int* __restrict__ etype,
           const float* __restrict__ conv_w, const float* __restrict__ conv_b,
           const float* __restrict__ fc_b,
           const float* __restrict__ bn1g, const float* __restrict__ bn1b,
           const float* __restrict__ bn1m, const float* __restrict__ bn1v,
           const float* __restrict__ bn3g, const float* __restrict__ bn3b,
           const float* __restrict__ bn3m, const float* __restrict__ bn3v,
           float* __restrict__ out)
{
    extern __shared__ char smc[];
    float* S3 = (float*)(smc + S3_OFF);
    float* Q3 = (float*)(smc + Q3_OFF);
    float* CA = (float*)(smc + CA_OFF);
    float* CB = (float*)(smc + CB_OFF);
    float* CD = (float*)(smc + CD_OFF);
    int* ROW = (int*)(smc + ROW_OFF);
    int* COL = (int*)(smc + COL_OFF);
    int* TYP = (int*)(smc + TYP_OFF);

    const uint32_t smem_base = smem_u32(smc);
    const uint32_t full0  = smem_base + MB_OFF;
    const uint32_t full1  = smem_base + MB_OFF + 8;
    const uint32_t empty0 = smem_base + MB_OFF + 16;
    const uint32_t empty1 = smem_base + MB_OFF + 24;

    const int tid = threadIdx.x;
    const int e0  = blockIdx.x * TILE_E;

    if (tid == 0) {
        mbar_init(full0, 64);     // producer threads arrive
        mbar_init(full1, 64);
        mbar_init(empty0, 256);   // consumer threads arrive
        mbar_init(empty1, 256);
    }
    if (tid < DDIM) {
        float s = bn3g[tid] * rsqrtf(bn3v[tid] + 1e-5f);
        S3[tid] = s;
        Q3[tid] = fc_b[tid] * s + bn3b[tid] - bn3m[tid] * s;
    }
    if (tid < TILE_E) {
        ROW[tid] = eidx[e0 + tid];
        COL[tid] = eidx[E_TOT + e0 + tid];
        TYP[tid] = etype[e0 + tid];
    }
    if (tid < 16) {
        float s1 = bn1g[0] * rsqrtf(bn1v[0] + 1e-5f);
        float b1 = bn1b[0] - bn1m[0] * s1;
        float w0 = conv_w[tid * 2], w1 = conv_w[tid * 2 + 1];
        CA[tid] = w0 * s1;
        CB[tid] = w1 * s1;
        CD[tid] = (w0 + w1) * b1 + conv_b[tid];
    }
    __syncthreads();

    if (tid >= 256) {
        // ================= PRODUCER (warps 8-9, 64 threads) =================
        const int ptid = tid - 256;       // 0..63
        const int pseg = ptid & 7;        // 16B k segment 0..7
        const int rsub = ptid >> 3;       // row subgroup 0..7

        // per-q (stored order) channel coeffs + j select; chunk-invariant
        float caq[4], cbq[4], cdq[4];
        int   jsel[4];
#pragma unroll
        for (int q = 0; q < 4; q++) {
            const int st = pseg * 4 + q;
            const int kl = (st & ~7) | ((st >> 1) & 3) | ((st & 1) << 2);
            const int c  = kl & 15;
            jsel[q] = kl >> 4;
            caq[q] = CA[c]; cbq[q] = CB[c]; cdq[q] = CD[c];
        }
        // edge rows handled by this thread for F (8 rows) + their gmem bases
        long ubase[8], vbase[8];
#pragma unroll
        for (int p = 0; p < 8; p++) {
            const int e = p * 8 + rsub;
            ubase[p] = (long)ROW[e] * DDIM;
            vbase[p] = (long)TYP[e] * DDIM;
        }

        int pph[2] = {1, 1};
        for (int chunk = 0; chunk < NCHUNKS; chunk++) {
            const int buf = chunk & 1;
            const int k0  = chunk * 32;
            const int j0  = chunk * 2;

            // prefetch u/v (L2) and first half of B before acquiring buffer
            float2 ur[8], vr[8];
#pragma unroll
            for (int p = 0; p < 8; p++) {
                ur[p] = __ldg((const float2*)(h + ubase[p] + j0));
                vr[p] = __ldg((const float2*)(g + vbase[p] + j0));
            }
            float4 breg[8];
#pragma unroll
            for (int p = 0; p < 8; p++) {
                const int n = p * 8 + rsub;
                breg[p] = __ldg((const float4*)&g_Bt[(long)n * KTOT + k0 + pseg * 4]);
            }

            mbar_wait(buf ? empty1 : empty0, pph[buf]);
            pph[buf] ^= 1;

            float* F  = (float*)(smc + (buf ? F1_OFF : F0_OFF));
            float* Bs = (float*)(smc + (buf ? B1_OFF : B0_OFF));

            // F rows (feat: folded bn1+conv, relu, tf32)
#pragma unroll
            for (int p = 0; p < 8; p++) {
                const int e = p * 8 + rsub;
                float fr[4];
#pragma unroll
                for (int q = 0; q < 4; q++) {
                    const float uu = jsel[q] ? ur[p].y : ur[p].x;
                    const float vv = jsel[q] ? vr[p].y : vr[p].x;
                    float f = fmaf(caq[q], uu, fmaf(cbq[q], vv, cdq[q]));
                    fr[q] = tf32r(fmaxf(f, 0.0f));
                }
                *(float4*)&F[e * FSTRIDE + pseg * 4] =
                    make_float4(fr[0], fr[1], fr[2], fr[3]);
            }
            // B rows: first half from prefetch, second half streamed
#pragma unroll
            for (int p = 0; p < 8; p++) {
                const int n = p * 8 + rsub;
                *(float4*)&Bs[n * FSTRIDE + pseg * 4] = breg[p];
            }
#pragma unroll
            for (int p = 0; p < 8; p++) {
                const int n = 64 + p * 8 + rsub;
                const float4 b4 = __ldg((const float4*)&g_Bt[(long)n * KTOT + k0 + pseg * 4]);
                *(float4*)&Bs[n * FSTRIDE + pseg * 4] = b4;
            }
            mbar_arrive(buf ? full1 : full0);
        }
    } else {
        // ================= CONSUMER (warps 0-7, 2m x 4n) =================
        const int wid  = tid >> 5;
        const int lane = tid & 31;
        const int gid  = lane >> 2;
        const int tig  = lane & 3;
        const int ebase = (wid & 1) * 32;
        const int nbase = (wid >> 1) * 32;

        float acc[2][4][4];
#pragma unroll
        for (int mt = 0; mt < 2; mt++)
#pragma unroll
            for (int nt = 0; nt < 4; nt++)
#pragma unroll
                for (int q = 0; q < 4; q++) acc[mt][nt][q] = 0.0f;

        int cph[2] = {0, 0};
        for (int chunk = 0; chunk < NCHUNKS; chunk++) {
            const int buf = chunk & 1;
            mbar_wait(buf ? full1 : full0, cph[buf]);
            cph[buf] ^= 1;

            const float* F  = (const float*)(smc + (buf ? F1_OFF : F0_OFF));
            const float* Bs = (const float*)(smc + (buf ? B1_OFF : B0_OFF));
#pragma unroll
            for (int ks = 0; ks < 32; ks += 8) {
                uint32_t a[2][4];
#pragma unroll
                for (int mt = 0; mt < 2; mt++) {
                    const int r = ebase + mt * 16 + gid;
                    const float2 fa = *(const float2*)&F[r * FSTRIDE + ks + 2 * tig];
                    const float2 fb = *(const float2*)&F[(r + 8) * FSTRIDE + ks + 2 * tig];
                    a[mt][0] = __float_as_uint(fa.x);
                    a[mt][1] = __float_as_uint(fb.x);
                    a[mt][2] = __float_as_uint(fa.y);
                    a[mt][3] = __float_as_uint(fb.y);
                }
#pragma unroll
                for (int nt = 0; nt < 4; nt++) {
                    const int n = nbase + nt * 8 + gid;
                    const float2 bb = *(const float2*)&Bs[n * FSTRIDE + ks + 2 * tig];
                    const uint32_t b0 = __float_as_uint(bb.x);
                    const uint32_t b1 = __float_as_uint(bb.y);
                    mma_tf32(acc[0][nt], a[0], b0, b1);
                    mma_tf32(acc[1][nt], a[1], b0, b1);
                }
            }
            mbar_arrive(buf ? empty1 : empty0);
        }

        // ---- epilogue: bn3 + relu + dot(h[col]) over this warp's 32-col slice ----
        long cbase[4];
#pragma unroll
        for (int rr = 0; rr < 4; rr++) {
            const int e = ebase + (rr >> 1) * 16 + (rr & 1) * 8 + gid;
            cbase[rr] = (long)COL[e] * DDIM;
        }
        float dotp[4] = {0.f, 0.f, 0.f, 0.f};
#pragma unroll
        for (int nt = 0; nt < 4; nt++) {
            const int n = nbase + nt * 8 + 2 * tig;
            const float2 s3 = *(const float2*)&S3[n];
            const float2 q3 = *(const float2*)&Q3[n];
#pragma unroll
            for (int mt = 0; mt < 2; mt++) {
#pragma unroll
                for (int hh = 0; hh < 2; hh++) {
                    const int rr = mt * 2 + hh;
                    float z0 = fmaxf(fmaf(acc[mt][nt][hh * 2 + 0], s3.x, q3.x), 0.0f);
                    float z1 = fmaxf(fmaf(acc[mt][nt][hh * 2 + 1], s3.y, q3.y), 0.0f);
                    const float2 c2 = __ldg((const float2*)(h + cbase[rr] + n));
                    dotp[rr] = fmaf(z0, c2.x, fmaf(z1, c2.y, dotp[rr]));
                }
            }
        }

        float* dsum = (float*)(smc + DS_OFF);
#pragma unroll
        for (int rr = 0; rr < 4; rr++) {
            float s = dotp[rr];
            s += __shfl_xor_sync(0xffffffffu, s, 1, 4);
            s += __shfl_xor_sync(0xffffffffu, s, 2, 4);
            if (tig == 0) {
                const int e = ebase + (rr >> 1) * 16 + (rr & 1) * 8 + gid;
                dsum[(wid >> 1) * TILE_E + e] = s;
            }
        }
    }

    __syncthreads();   // join producers + consumers; dsum visible
    if (tid < TILE_E) {
        const float* ds = (const float*)(smc + DS_OFF);
        out[e0 + tid] = (ds[tid] + ds[TILE_E + tid]) +
                        (ds[2 * TILE_E + tid] + ds[3 * TILE_E + tid]);
    }
}

// ===== launch =====
extern "C" void kernel_launch(void* const* d_in, const int* in_sizes, int n_in,
                              void* d_out, int out_size)
{
    const float* h      = (const float*)d_in[0];
    const float* g      = (const float*)d_in[1];
    const int*   eidx   = (const int*)d_in[2];
    const int*   etype  = (const int*)d_in[3];
    const float* conv_w = (const float*)d_in[4];
    const float* conv_b = (const float*)d_in[5];
    const float* fc_w   = (const float*)d_in[6];
    const float* fc_b   = (const float*)d_in[7];
    const float* bn1g   = (const float*)d_in[8];
    const float* bn1b   = (const float*)d_in[9];
    const float* bn1m   = (const float*)d_in[10];
    const float* bn1v   = (const float*)d_in[11];
    const float* bn3g   = (const float*)d_in[12];
    const float* bn3b   = (const float*)d_in[13];
    const float* bn3m   = (const float*)d_in[14];
    const float* bn3v   = (const float*)d_in[15];
    float* out = (float*)d_out;

    dim3 pgrid(KTOT / 32, DDIM / 32);
    conve_prep<<<pgrid, 256>>>(fc_w);

    cudaFuncSetAttribute(conve_main,
                         cudaFuncAttributeMaxDynamicSharedMemorySize, SMEM_BYTES);
    conve_main<<<E_TOT / TILE_E, NTHREADS, SMEM_BYTES>>>(
        h, g, eidx, etype, conv_w, conv_b, fc_b,
        bn1g, bn1b, bn1m, bn1v, bn3g, bn3b, bn3m, bn3v, out);
}